// round 2
// baseline (speedup 1.0000x reference)
#include <cuda_runtime.h>

// RandomShiftsAug == integer shifted gather with edge clamp:
//   out[n,c,j,i] = x[n,c, clamp(j+sy-4,0,83), clamp(i+sx-4,0,83)]
//
// Strategy: stage each (n,c) 84x84 slice in shared memory.
//   - global read : aligned float4, perfectly coalesced
//   - shift       : resolved via smem indexing (clamped scalar LDS)
//   - global write: aligned float4, perfectly coalesced
// Pure HBM-bound: 130 MB in + 130 MB out.

#define N_   512
#define C_   9
#define H_   84
#define W_   84
#define PAD_ 4

#define SLICE   (H_ * W_)        // 7056 floats
#define SLICE4  (SLICE / 4)      // 1764 float4
#define W4      (W_ / 4)         // 21 float4 per row
#define THREADS 256

__global__ __launch_bounds__(THREADS) void random_shift_smem_kernel(
    const float* __restrict__ x,
    const int*   __restrict__ shift,
    float*       __restrict__ out)
{
    __shared__ float s[SLICE];

    const int nc = blockIdx.x;           // 0 .. N_*C_-1
    const int n  = nc / C_;
    const int tid = threadIdx.x;

    // ---- stage input slice: aligned float4, fully coalesced ----
    const float4* __restrict__ src4 = reinterpret_cast<const float4*>(x) + (long)nc * SLICE4;
    float4* __restrict__ s4 = reinterpret_cast<float4*>(s);
    #pragma unroll
    for (int k = tid; k < SLICE4; k += THREADS)
        s4[k] = src4[k];

    const int sx = __ldg(&shift[2 * n + 0]) - PAD_;   // in [-4, 4]
    const int sy = __ldg(&shift[2 * n + 1]) - PAD_;

    __syncthreads();

    // ---- shifted write: aligned float4, fully coalesced ----
    float4* __restrict__ dst4 = reinterpret_cast<float4*>(out) + (long)nc * SLICE4;

    #pragma unroll
    for (int k = tid; k < SLICE4; k += THREADS) {
        int j = k / W4;                  // output row
        int q = k - j * W4;              // float4 chunk within row

        int srcy = min(max(j + sy, 0), H_ - 1);
        const float* __restrict__ row = s + srcy * W_;

        int a = q * 4 + sx;              // first source column, in [-4, 87]
        float4 v;
        v.x = row[min(max(a + 0, 0), W_ - 1)];
        v.y = row[min(max(a + 1, 0), W_ - 1)];
        v.z = row[min(max(a + 2, 0), W_ - 1)];
        v.w = row[min(max(a + 3, 0), W_ - 1)];

        dst4[k] = v;
    }
}

extern "C" void kernel_launch(void* const* d_in, const int* in_sizes, int n_in,
                              void* d_out, int out_size)
{
    const float* x     = (const float*)d_in[0];
    const int*   shift = (const int*)  d_in[1];
    float* out = (float*)d_out;

    random_shift_smem_kernel<<<N_ * C_, THREADS>>>(x, shift, out);
}